// round 1
// baseline (speedup 1.0000x reference)
#include <cuda_runtime.h>
#include <math_constants.h>
#include <cstddef>

// Problem shape (fixed by reference)
#define BB  4
#define SS  2048
#define EE  1024
#define HH  64
#define NROWS (BB*SS)     // 8192 total query rows
#define CH  128           // keys per split-K chunk
#define NCH (SS/CH)       // 16 chunks per batch

// -------- device scratch (no allocations allowed in kernel_launch) --------
__device__ float g_q[NROWS*HH];
__device__ float g_k[NROWS*HH];
__device__ float g_v[NROWS*HH];
__device__ float g_opart[(size_t)NROWS*NCH*HH];   // unnormalized partial outputs
__device__ float g_ml[(size_t)NROWS*NCH*2];       // per-chunk (m, l)

// ==========================================================================
// Kernel 1: fused QKV projection.  x:[8192,1024] @ W[1024,64] -> q/k/v:[8192,64]
// Block: 256 threads, computes 64 rows x 64 cols for all three matrices.
// ==========================================================================
__global__ __launch_bounds__(256) void qkv_proj(
    const float* __restrict__ x,
    const float* __restrict__ Wq, const float* __restrict__ bq,
    const float* __restrict__ Wk, const float* __restrict__ bk,
    const float* __restrict__ Wv, const float* __restrict__ bv)
{
    __shared__ float xs[64][17];          // +1 pad to break bank conflicts
    __shared__ float wqs[16][64];
    __shared__ float wks[16][64];
    __shared__ float wvs[16][64];

    const int tid = threadIdx.x;
    const int ty  = tid >> 4;             // 0..15 -> row group
    const int tx  = tid & 15;             // 0..15 -> col group
    const int row0 = blockIdx.x * 64;

    float accq[4][4] = {};
    float acck[4][4] = {};
    float accv[4][4] = {};

    for (int kb = 0; kb < EE; kb += 16) {
        // load x tile: 64x16 floats, 4 per thread (contiguous float4 in e)
        {
            int idx = tid * 4;
            int rr = idx >> 4;
            int cc = idx & 15;
            float4 t = *(const float4*)&x[(size_t)(row0 + rr) * EE + kb + cc];
            xs[rr][cc+0] = t.x; xs[rr][cc+1] = t.y;
            xs[rr][cc+2] = t.z; xs[rr][cc+3] = t.w;
        }
        // load W tiles: each 16x64, 4 per thread
        {
            int idx = tid * 4;
            int rr = idx >> 6;
            int cc = idx & 63;
            *(float4*)&wqs[rr][cc] = *(const float4*)&Wq[(size_t)(kb + rr) * HH + cc];
            *(float4*)&wks[rr][cc] = *(const float4*)&Wk[(size_t)(kb + rr) * HH + cc];
            *(float4*)&wvs[rr][cc] = *(const float4*)&Wv[(size_t)(kb + rr) * HH + cc];
        }
        __syncthreads();

        #pragma unroll
        for (int kk = 0; kk < 16; kk++) {
            float a[4];
            #pragma unroll
            for (int i = 0; i < 4; i++) a[i] = xs[ty*4 + i][kk];
            float4 wq4 = *(const float4*)&wqs[kk][tx*4];
            float4 wk4 = *(const float4*)&wks[kk][tx*4];
            float4 wv4 = *(const float4*)&wvs[kk][tx*4];
            #pragma unroll
            for (int i = 0; i < 4; i++) {
                accq[i][0] = fmaf(a[i], wq4.x, accq[i][0]);
                accq[i][1] = fmaf(a[i], wq4.y, accq[i][1]);
                accq[i][2] = fmaf(a[i], wq4.z, accq[i][2]);
                accq[i][3] = fmaf(a[i], wq4.w, accq[i][3]);
                acck[i][0] = fmaf(a[i], wk4.x, acck[i][0]);
                acck[i][1] = fmaf(a[i], wk4.y, acck[i][1]);
                acck[i][2] = fmaf(a[i], wk4.z, acck[i][2]);
                acck[i][3] = fmaf(a[i], wk4.w, acck[i][3]);
                accv[i][0] = fmaf(a[i], wv4.x, accv[i][0]);
                accv[i][1] = fmaf(a[i], wv4.y, accv[i][1]);
                accv[i][2] = fmaf(a[i], wv4.z, accv[i][2]);
                accv[i][3] = fmaf(a[i], wv4.w, accv[i][3]);
            }
        }
        __syncthreads();
    }

    float4 biasq = *(const float4*)&bq[tx*4];
    float4 biask = *(const float4*)&bk[tx*4];
    float4 biasv = *(const float4*)&bv[tx*4];

    #pragma unroll
    for (int i = 0; i < 4; i++) {
        size_t off = (size_t)(row0 + ty*4 + i) * HH + tx*4;
        float4 oq = make_float4(accq[i][0] + biasq.x, accq[i][1] + biasq.y,
                                accq[i][2] + biasq.z, accq[i][3] + biasq.w);
        float4 ok = make_float4(acck[i][0] + biask.x, acck[i][1] + biask.y,
                                acck[i][2] + biask.z, acck[i][3] + biask.w);
        float4 ov = make_float4(accv[i][0] + biasv.x, accv[i][1] + biasv.y,
                                accv[i][2] + biasv.z, accv[i][3] + biasv.w);
        *(float4*)&g_q[off] = oq;
        *(float4*)&g_k[off] = ok;
        *(float4*)&g_v[off] = ov;
    }
}

// ==========================================================================
// Kernel 2: split-K causal flash attention, phase 1 (partials per key chunk).
// Grid (qtile=32, chunk=16, batch=4); block = 64 threads, one query row each.
// ==========================================================================
__global__ __launch_bounds__(64) void attn_partial()
{
    __shared__ float ks[64][64];
    __shared__ float vs[64][64];

    const int tid = threadIdx.x;
    const int qt  = blockIdx.x;
    const int c   = blockIdx.y;
    const int b   = blockIdx.z;

    // whole block below the causal diagonal for this chunk -> no work
    if (c * CH > qt * 64 + 63) return;

    const int i = qt * 64 + tid;          // query position within batch
    const size_t r = (size_t)b * SS + i;  // global row

    float qreg[HH];
    #pragma unroll
    for (int e = 0; e < HH; e += 4) {
        float4 t = *(const float4*)&g_q[r * HH + e];
        qreg[e+0] = t.x; qreg[e+1] = t.y; qreg[e+2] = t.z; qreg[e+3] = t.w;
    }

    float o[HH];
    #pragma unroll
    for (int e = 0; e < HH; e++) o[e] = 0.0f;
    float m = -CUDART_INF_F;
    float l = 0.0f;

    #pragma unroll 1
    for (int sub = 0; sub < 2; sub++) {
        const int k0 = c * CH + sub * 64;       // first key in sub-tile
        __syncthreads();
        {   // cooperative load: thread t fetches key row k0+t (always < SS)
            const float* kp = &g_k[((size_t)b * SS + k0 + tid) * HH];
            const float* vp = &g_v[((size_t)b * SS + k0 + tid) * HH];
            #pragma unroll
            for (int e = 0; e < HH; e += 4) {
                *(float4*)&ks[tid][e] = *(const float4*)&kp[e];
                *(float4*)&vs[tid][e] = *(const float4*)&vp[e];
            }
        }
        __syncthreads();

        const int nj = min(63, i - k0);         // causal bound inside sub-tile
        for (int jj = 0; jj <= nj; jj++) {
            // dot(q, K[jj]) with 4 partial sums to break the FMA chain
            float s0 = 0.f, s1 = 0.f, s2 = 0.f, s3 = 0.f;
            #pragma unroll
            for (int e = 0; e < HH; e += 4) {
                float4 kk4 = *(const float4*)&ks[jj][e];
                s0 = fmaf(qreg[e+0], kk4.x, s0);
                s1 = fmaf(qreg[e+1], kk4.y, s1);
                s2 = fmaf(qreg[e+2], kk4.z, s2);
                s3 = fmaf(qreg[e+3], kk4.w, s3);
            }
            float s = ((s0 + s1) + (s2 + s3)) * 0.125f;   // 1/sqrt(64)

            if (s > m) {
                // rare path: rescale accumulators (first key: m=-inf -> alpha=0)
                float alpha = __expf(m - s);
                l = l * alpha + 1.0f;
                #pragma unroll
                for (int e = 0; e < HH; e += 4) {
                    float4 vv = *(const float4*)&vs[jj][e];
                    o[e+0] = o[e+0] * alpha + vv.x;
                    o[e+1] = o[e+1] * alpha + vv.y;
                    o[e+2] = o[e+2] * alpha + vv.z;
                    o[e+3] = o[e+3] * alpha + vv.w;
                }
                m = s;
            } else {
                // common path: 1 FMA per element
                float p = __expf(s - m);
                l += p;
                #pragma unroll
                for (int e = 0; e < HH; e += 4) {
                    float4 vv = *(const float4*)&vs[jj][e];
                    o[e+0] = fmaf(p, vv.x, o[e+0]);
                    o[e+1] = fmaf(p, vv.y, o[e+1]);
                    o[e+2] = fmaf(p, vv.z, o[e+2]);
                    o[e+3] = fmaf(p, vv.w, o[e+3]);
                }
            }
        }
    }

    // write partials (threads with no valid keys write m=-inf, l=0, o=0)
    const size_t base = (r * NCH + c) * HH;
    #pragma unroll
    for (int e = 0; e < HH; e += 4) {
        *(float4*)&g_opart[base + e] = make_float4(o[e], o[e+1], o[e+2], o[e+3]);
    }
    g_ml[(r * NCH + c) * 2 + 0] = m;
    g_ml[(r * NCH + c) * 2 + 1] = l;
}

// ==========================================================================
// Kernel 3: combine split-K partials.  One block per query row, thread = h.
// ==========================================================================
__global__ __launch_bounds__(64) void attn_combine(float* __restrict__ out)
{
    const size_t r = blockIdx.x;          // 0..8191
    const int    i = (int)(r & (SS - 1)); // position within batch
    const int    e = threadIdx.x;
    const int  nch = i / CH + 1;          // valid chunks for this row

    float M = -CUDART_INF_F;
    #pragma unroll 1
    for (int c = 0; c < nch; c++)
        M = fmaxf(M, g_ml[(r * NCH + c) * 2 + 0]);

    float L = 0.0f, o = 0.0f;
    #pragma unroll 1
    for (int c = 0; c < nch; c++) {
        float mc = g_ml[(r * NCH + c) * 2 + 0];
        float lc = g_ml[(r * NCH + c) * 2 + 1];
        float w  = __expf(mc - M);        // mc=-inf -> w=0 (empty partial)
        L += lc * w;
        o  = fmaf(w, g_opart[(r * NCH + c) * HH + e], o);
    }
    out[r * HH + e] = o / L;
}

// ==========================================================================
extern "C" void kernel_launch(void* const* d_in, const int* in_sizes, int n_in,
                              void* d_out, int out_size)
{
    const float* x  = (const float*)d_in[0];
    const float* Wq = (const float*)d_in[1];
    const float* bq = (const float*)d_in[2];
    const float* Wk = (const float*)d_in[3];
    const float* bk = (const float*)d_in[4];
    const float* Wv = (const float*)d_in[5];
    const float* bv = (const float*)d_in[6];
    float* out = (float*)d_out;

    qkv_proj<<<NROWS / 64, 256>>>(x, Wq, bq, Wk, bk, Wv, bv);

    dim3 g(SS / 64, NCH, BB);
    attn_partial<<<g, 64>>>();

    attn_combine<<<NROWS, 64>>>(out);
}